// round 3
// baseline (speedup 1.0000x reference)
#include <cuda_runtime.h>
#include <math.h>

#define N 1024
#define NN (N*N)
#define NB 32

// ---------------- scratch (device globals; no allocations allowed) -------------
__device__ float g_lu[16 * NN];      // 64 MB LU workspace (copy of x)
__device__ float g_y[3 * NN];        // 12 MB combined B operand
__device__ float g_part[2 * NN];     // 8 MB split-K partials
__device__ float g_scores[16];
__device__ int   g_piv[16 * NB];
__device__ int   g_top[8];
__device__ int   g_gate;
__device__ float g_weff[11];         // [0..5] pair weights, [6..9] preserve, [10] bias

// ---------------- init: copy x -> g_lu, zero scores ----------------------------
__global__ void init_kernel(const float4* __restrict__ x4) {
    size_t n4 = (size_t)16 * NN / 4;
    for (size_t i = (size_t)blockIdx.x * blockDim.x + threadIdx.x; i < n4;
         i += (size_t)gridDim.x * blockDim.x)
        ((float4*)g_lu)[i] = x4[i];
    if (blockIdx.x == 0 && threadIdx.x < 16) g_scores[threadIdx.x] = 0.0f;
}

// ---------------- LU panel: factor N-k x 32 panel in smem with pivoting --------
__global__ void panel_kernel(int kb) {
    extern __shared__ float sp[];           // [R][33] padded
    __shared__ float rv[8];
    __shared__ int   rr[8];
    __shared__ int   s_piv;
    __shared__ float s_u;
    __shared__ int   spiv[NB];
    int m = blockIdx.x;
    float* A = g_lu + (size_t)m * NN;
    int col0 = kb * NB;
    int R = N - col0;
    int tid = threadIdx.x;

    for (int l = tid; l < R * NB; l += 256) {
        int r = l >> 5, c = l & 31;
        sp[r * 33 + c] = A[(size_t)(col0 + r) * N + col0 + c];
    }
    __syncthreads();

    float logsum = 0.0f;
    for (int j = 0; j < NB; j++) {
        // pivot search: argmax |sp[r][j]| for r in [j, R)
        float bv = -1.0f; int br = j;
        for (int r = j + tid; r < R; r += 256) {
            float v = fabsf(sp[r * 33 + j]);
            if (v > bv) { bv = v; br = r; }
        }
        #pragma unroll
        for (int off = 16; off; off >>= 1) {
            float ov = __shfl_down_sync(0xffffffffu, bv, off);
            int   orr = __shfl_down_sync(0xffffffffu, br, off);
            if (ov > bv || (ov == bv && orr < br)) { bv = ov; br = orr; }
        }
        if ((tid & 31) == 0) { rv[tid >> 5] = bv; rr[tid >> 5] = br; }
        __syncthreads();
        if (tid == 0) {
            float b0 = rv[0]; int r0 = rr[0];
            for (int w = 1; w < 8; w++)
                if (rv[w] > b0 || (rv[w] == b0 && rr[w] < r0)) { b0 = rv[w]; r0 = rr[w]; }
            s_piv = r0;
            s_u = sp[r0 * 33 + j];
            spiv[j] = col0 + r0;
            logsum += logf(fabsf(s_u));
        }
        __syncthreads();
        int pr = s_piv;
        float u = s_u;
        if (tid < NB && pr != j) {
            float t = sp[j * 33 + tid];
            sp[j * 33 + tid] = sp[pr * 33 + tid];
            sp[pr * 33 + tid] = t;
        }
        __syncthreads();
        float inv = 1.0f / u;
        for (int r = j + 1 + tid; r < R; r += 256) {
            float lij = sp[r * 33 + j] * inv;
            sp[r * 33 + j] = lij;
            for (int c2 = j + 1; c2 < NB; c2++)
                sp[r * 33 + c2] -= lij * sp[j * 33 + c2];
        }
        __syncthreads();
    }

    for (int l = tid; l < R * NB; l += 256) {
        int r = l >> 5, c = l & 31;
        A[(size_t)(col0 + r) * N + col0 + c] = sp[r * 33 + c];
    }
    if (tid < NB) g_piv[m * NB + tid] = spiv[tid];
    if (tid == 0) g_scores[m] += logsum;
}

// ---------------- row swaps (trailing cols) + TRSM: U12 = L11^{-1} A12 --------
__global__ void trsm_kernel(int kb) {
    int m = blockIdx.y;
    float* A = g_lu + (size_t)m * NN;
    int col0 = kb * NB;
    __shared__ float Ls[32][33];
    for (int l = threadIdx.x; l < 32 * 32; l += blockDim.x)
        Ls[l >> 5][l & 31] = A[(size_t)(col0 + (l >> 5)) * N + col0 + (l & 31)];
    __syncthreads();

    int c = col0 + NB + blockIdx.x * blockDim.x + threadIdx.x;
    if (c >= N) return;

    #pragma unroll
    for (int j = 0; j < NB; j++) {
        int pr = g_piv[m * NB + j];
        int rj = col0 + j;
        if (pr != rj) {
            float t = A[(size_t)rj * N + c];
            A[(size_t)rj * N + c] = A[(size_t)pr * N + c];
            A[(size_t)pr * N + c] = t;
        }
    }
    float u[32];
    #pragma unroll
    for (int j = 0; j < 32; j++) {
        float s = A[(size_t)(col0 + j) * N + c];
        #pragma unroll
        for (int i = 0; i < j; i++) s -= Ls[j][i] * u[i];
        u[j] = s;
        A[(size_t)(col0 + j) * N + c] = s;
    }
}

// ---------------- trailing update: A22 -= L21 @ U12  (64x64 tiles, k=32) ------
__global__ void update_kernel(int kb) {
    int m = blockIdx.z;
    float* A = g_lu + (size_t)m * NN;
    int col0 = kb * NB;
    int base = col0 + NB;
    int row0 = base + blockIdx.y * 64;
    int c0   = base + blockIdx.x * 64;
    __shared__ float LsT[32][68];   // k-major, padded
    __shared__ float Us[32][64];
    int tid = threadIdx.x;

    for (int l = tid; l < 64 * 32; l += 256) {
        int r = l >> 5, kk = l & 31;
        float v = (row0 + r < N) ? A[(size_t)(row0 + r) * N + col0 + kk] : 0.0f;
        LsT[kk][r] = v;
    }
    for (int l = tid; l < 32 * 64; l += 256) {
        int cc = l & 63, kk = l >> 6;
        float v = (c0 + cc < N) ? A[(size_t)(col0 + kk) * N + c0 + cc] : 0.0f;
        Us[kk][cc] = v;
    }
    __syncthreads();

    int tx = tid & 15, ty = tid >> 4;
    float acc[4][4] = {};
    #pragma unroll
    for (int kk = 0; kk < 32; kk++) {
        float4 a = *(const float4*)&LsT[kk][ty * 4];
        float4 b = *(const float4*)&Us[kk][tx * 4];
        float av[4] = {a.x, a.y, a.z, a.w};
        float bv[4] = {b.x, b.y, b.z, b.w};
        #pragma unroll
        for (int i = 0; i < 4; i++)
            #pragma unroll
            for (int j = 0; j < 4; j++)
                acc[i][j] = fmaf(av[i], bv[j], acc[i][j]);
    }
    int r0 = row0 + ty * 4, cc0 = c0 + tx * 4;
    if (cc0 < N) {
        #pragma unroll
        for (int i = 0; i < 4; i++) {
            int r = r0 + i;
            if (r < N) {
                float4* p = (float4*)&A[(size_t)r * N + cc0];
                float4 v = *p;
                v.x -= acc[i][0]; v.y -= acc[i][1]; v.z -= acc[i][2]; v.w -= acc[i][3];
                *p = v;
            }
        }
    }
}

// ---------------- top-8 selection + effective-weight collapse -----------------
// flags buffer dtype is unknown (bool->uint8 or bool->int32). Decode adaptively:
// read the first int32 word; if it is >1 (e.g. 0x01010101 packed bools) decode
// as bytes, otherwise decode as int32 words. Correct for all-true / all-false
// in both encodings.
__global__ void topk_kernel(const int* __restrict__ flags_i32,
                            const float* __restrict__ W1, const float* __restrict__ b1,
                            const float* __restrict__ W2, const float* __restrict__ b2) {
    if (threadIdx.x != 0) return;
    const unsigned char* flags_u8 = (const unsigned char*)flags_i32;
    int w0 = flags_i32[0];
    bool as_bytes = (w0 > 1) || (w0 < 0);
    int f[16];
    for (int i = 0; i < 16; i++)
        f[i] = as_bytes ? (flags_u8[i] != 0) : (flags_i32[i] != 0);

    int s = 0;
    for (int i = 0; i < 16; i++) s += f[i];
    int gate = (s >= 4) ? 1 : 0;
    g_gate = gate;
    const float NEG_INF = -__int_as_float(0x7f800000);
    float sc[16];
    for (int i = 0; i < 16; i++)
        sc[i] = f[i] ? g_scores[i] : NEG_INF;
    bool used[16] = {};
    for (int k = 0; k < 8; k++) {
        float best = NEG_INF;
        int bi = -1;
        for (int i = 0; i < 16; i++)
            if (!used[i] && (bi < 0 || sc[i] > best)) { best = sc[i]; bi = i; }
        used[bi] = true;
        g_top[k] = bi;
    }
    for (int c = 0; c < 10; c++) {
        float a = 0.0f;
        for (int h = 0; h < 16; h++) a += W2[h] * W1[h * 10 + c];
        g_weff[c] = a;
    }
    float be = b2[0];
    for (int h = 0; h < 16; h++) be += W2[h] * b1[h];
    g_weff[10] = be;
}

// ---------------- Y combos: Y_i = sum_{j>i} w_p X_j ---------------------------
__global__ void ycombo_kernel(const float* __restrict__ x) {
    const float* X1 = x + (size_t)g_top[1] * NN;
    const float* X2 = x + (size_t)g_top[2] * NN;
    const float* X3 = x + (size_t)g_top[3] * NN;
    float w0 = g_weff[0], w1 = g_weff[1], w2 = g_weff[2];
    float w3 = g_weff[3], w4 = g_weff[4], w5 = g_weff[5];
    for (int e = blockIdx.x * blockDim.x + threadIdx.x; e < NN;
         e += gridDim.x * blockDim.x) {
        float a = X1[e], b = X2[e], c = X3[e];
        g_y[e]            = w0 * a + w1 * b + w2 * c;
        g_y[NN + e]       = w3 * b + w4 * c;
        g_y[2 * NN + e]   = w5 * c;
    }
}

// ---------------- one big GEMM: part_z = X[0..2] (1024x3072) @ Y (3072x1024) --
__global__ __launch_bounds__(256) void pair_gemm(const float* __restrict__ x) {
    __shared__ float As[16][132];
    __shared__ float Bs[16][128];
    int z = blockIdx.z;
    int row0 = blockIdx.y * 128, c0 = blockIdx.x * 128;
    const float* A0 = x + (size_t)g_top[0] * NN;
    const float* A1 = x + (size_t)g_top[1] * NN;
    const float* A2 = x + (size_t)g_top[2] * NN;
    int tid = threadIdx.x;
    float acc[8][8] = {};
    int k0 = z * 1536;
    for (int kt = 0; kt < 96; kt++) {
        int kg = k0 + kt * 16;
        const float* Ap = (kg < 1024) ? A0 : ((kg < 2048) ? A1 : A2);
        int kl = kg & 1023;
        #pragma unroll
        for (int i = 0; i < 8; i++) {
            int l = tid + i * 256;
            int kk = l & 15, mm = l >> 4;
            As[kk][mm] = Ap[(size_t)(row0 + mm) * N + kl + kk];
        }
        #pragma unroll
        for (int i = 0; i < 8; i++) {
            int l = tid + i * 256;
            int nn = l & 127, kk = l >> 7;
            Bs[kk][nn] = g_y[(size_t)(kg + kk) * N + c0 + nn];
        }
        __syncthreads();
        int mm0 = (tid >> 4) * 8, nn0 = (tid & 15) * 8;
        #pragma unroll
        for (int kk = 0; kk < 16; kk++) {
            float a[8], b[8];
            *(float4*)&a[0] = *(const float4*)&As[kk][mm0];
            *(float4*)&a[4] = *(const float4*)&As[kk][mm0 + 4];
            *(float4*)&b[0] = *(const float4*)&Bs[kk][nn0];
            *(float4*)&b[4] = *(const float4*)&Bs[kk][nn0 + 4];
            #pragma unroll
            for (int i = 0; i < 8; i++)
                #pragma unroll
                for (int j = 0; j < 8; j++)
                    acc[i][j] = fmaf(a[i], b[j], acc[i][j]);
        }
        __syncthreads();
    }
    float* P = g_part + (size_t)z * NN;
    int mm0 = (tid >> 4) * 8, nn0 = (tid & 15) * 8;
    #pragma unroll
    for (int i = 0; i < 8; i++) {
        float4 v0 = {acc[i][0], acc[i][1], acc[i][2], acc[i][3]};
        float4 v1 = {acc[i][4], acc[i][5], acc[i][6], acc[i][7]};
        size_t off = (size_t)(row0 + mm0 + i) * N + c0 + nn0;
        *(float4*)&P[off] = v0;
        *(float4*)&P[off + 4] = v1;
    }
}

// ---------------- epilogue: preserve terms + bias + swish ---------------------
__global__ void final_kernel(const float* __restrict__ x, float* __restrict__ out,
                             int out_size) {
    int gate = g_gate;
    const float* P4 = x + (size_t)g_top[4] * NN;
    const float* P5 = x + (size_t)g_top[5] * NN;
    const float* P6 = x + (size_t)g_top[6] * NN;
    const float* P7 = x + (size_t)g_top[7] * NN;
    float w6 = g_weff[6], w7 = g_weff[7], w8 = g_weff[8], w9 = g_weff[9];
    float be = g_weff[10];
    for (int i = blockIdx.x * blockDim.x + threadIdx.x; i < out_size;
         i += gridDim.x * blockDim.x) {
        if (i < NN) {
            float s = g_part[i] + g_part[NN + i]
                    + w6 * P4[i] + w7 * P5[i] + w8 * P6[i] + w9 * P7[i] + be;
            float r = gate ? (s / (1.0f + expf(-s))) : 0.0f;
            out[i] = r;
        } else {
            out[i] = gate ? 1.0f : 0.0f;
        }
    }
}

// ---------------- host driver (graph-capturable: launches only) ---------------
extern "C" void kernel_launch(void* const* d_in, const int* in_sizes, int n_in,
                              void* d_out, int out_size) {
    const float* x = (const float*)d_in[0];
    const int* flags = (const int*)d_in[1];
    const float* W1 = (const float*)d_in[2];
    const float* b1 = (const float*)d_in[3];
    const float* W2 = (const float*)d_in[4];
    const float* b2 = (const float*)d_in[5];
    float* out = (float*)d_out;

    cudaFuncSetAttribute(panel_kernel, cudaFuncAttributeMaxDynamicSharedMemorySize,
                         N * 33 * 4);

    init_kernel<<<2048, 256>>>((const float4*)x);

    for (int kb = 0; kb < 32; kb++) {
        int col0 = kb * NB;
        int R = N - col0;
        panel_kernel<<<16, 256, (size_t)R * 33 * 4>>>(kb);
        int W = N - col0 - NB;
        if (W > 0) {
            trsm_kernel<<<dim3((W + 127) / 128, 16), 128>>>(kb);
            int Wt = (W + 63) / 64;
            update_kernel<<<dim3(Wt, Wt, 16), 256>>>(kb);
        }
    }

    topk_kernel<<<1, 32>>>(flags, W1, b1, W2, b2);
    ycombo_kernel<<<1024, 256>>>(x);
    pair_gemm<<<dim3(8, 8, 2), 256>>>(x);
    final_kernel<<<1024, 256>>>(x, out, out_size);
}

// round 7
// speedup vs baseline: 1.0929x; 1.0929x over previous
#include <cuda_runtime.h>
#include <math.h>

#define N 1024
#define NN (N*N)
#define NB 32
#define NSTEP 27           // steps kb=0..26 ; panels 0..27 ; tail = last 128 cols

// ---------------- scratch (device globals; no allocations allowed) -------------
__device__ float g_lu[16 * NN];      // 64 MB LU workspace
__device__ float g_y[3 * NN];        // combined B operand
__device__ float g_part[2 * NN];     // split-K partials
__device__ float g_scores[16];
__device__ int   g_piv[2][16][NB];   // ping-pong by panel parity
__device__ int   g_top[8];
__device__ int   g_gate;
__device__ float g_weff[11];

// ---------------- init: copy x -> g_lu ----------------------------------------
__global__ void init_kernel(const float4* __restrict__ x4) {
    size_t n4 = (size_t)16 * NN / 4;
    for (size_t i = (size_t)blockIdx.x * blockDim.x + threadIdx.x; i < n4;
         i += (size_t)gridDim.x * blockDim.x)
        ((float4*)g_lu)[i] = x4[i];
}

// ---------------- shared panel factorization (R x 32 in smem, stride 33) ------
__device__ void factor_inplace(float* sp, int R, int m, int abs0, int parity,
                               bool first) {
    __shared__ float rv[8];
    __shared__ int   rr[8];
    __shared__ float s_u;
    __shared__ int   s_p;
    __shared__ int   spiv[NB];
    int tid = threadIdx.x;
    float logsum = 0.0f;
    for (int j = 0; j < NB; j++) {
        float bv = -1.0f; int br = j;
        for (int r = j + tid; r < R; r += 256) {
            float v = fabsf(sp[r * 33 + j]);
            if (v > bv) { bv = v; br = r; }
        }
        #pragma unroll
        for (int off = 16; off; off >>= 1) {
            float ov = __shfl_down_sync(0xffffffffu, bv, off);
            int   orr = __shfl_down_sync(0xffffffffu, br, off);
            if (ov > bv || (ov == bv && orr < br)) { bv = ov; br = orr; }
        }
        if ((tid & 31) == 0) { rv[tid >> 5] = bv; rr[tid >> 5] = br; }
        __syncthreads();
        if (tid == 0) {
            float b0 = rv[0]; int r0 = rr[0];
            for (int w = 1; w < 8; w++)
                if (rv[w] > b0 || (rv[w] == b0 && rr[w] < r0)) { b0 = rv[w]; r0 = rr[w]; }
            s_p = r0;
            s_u = sp[r0 * 33 + j];
            spiv[j] = abs0 + r0;
            logsum += logf(fabsf(s_u));
        }
        __syncthreads();
        int p = s_p;
        float u = s_u;
        if (tid < NB && p != j) {
            float t = sp[j * 33 + tid];
            sp[j * 33 + tid] = sp[p * 33 + tid];
            sp[p * 33 + tid] = t;
        }
        __syncthreads();
        float inv = 1.0f / u;
        for (int r = j + 1 + tid; r < R; r += 256) {
            float lij = sp[r * 33 + j] * inv;
            sp[r * 33 + j] = lij;
            for (int c = j + 1; c < NB; c++)
                sp[r * 33 + c] -= lij * sp[j * 33 + c];
        }
        __syncthreads();
    }
    if (tid < NB) g_piv[parity][m][tid] = spiv[tid];
    if (tid == 0) {
        if (first) g_scores[m] = logsum;
        else       g_scores[m] += logsum;
    }
}

// ---------------- panel 0 ------------------------------------------------------
__global__ __launch_bounds__(256) void panel0_kernel() {
    extern __shared__ float sp[];       // 1024 x 33
    int m = blockIdx.x, tid = threadIdx.x;
    float* A = g_lu + (size_t)m * NN;
    for (int l = tid; l < N * 32; l += 256) {
        int r = l >> 5, c = l & 31;
        sp[r * 33 + c] = A[(size_t)r * N + c];
    }
    __syncthreads();
    factor_inplace(sp, N, m, 0, 0, true);
    __syncthreads();
    for (int l = tid; l < N * 32; l += 256) {
        int r = l >> 5, c = l & 31;
        A[(size_t)r * N + c] = sp[r * 33 + c];
    }
}

// ---------------- fused LU step: swaps + trsm + update (+ next panel) ----------
// grid: (1 + nrest, 16). block x==0 = combo (next panel cols), else 128-col strip.
__global__ __launch_bounds__(256) void step_kernel(int kb) {
    extern __shared__ float sm[];
    __shared__ int rA[32], rB[32];
    __shared__ int dsts[64], srcs[64];
    __shared__ int s_cnt;
    int tid = threadIdx.x, m = blockIdx.y;
    float* A = g_lu + (size_t)m * NN;
    int col0 = kb * NB, nb0 = col0 + NB;
    int par = kb & 1;

    if (tid < 32) { rA[tid] = col0 + tid; rB[tid] = g_piv[par][m][tid]; }
    if (tid == 0) s_cnt = 0;
    __syncthreads();
    // build (dst,src) row-permutation list from the 32 sequential swaps
    if (tid < 64) {
        int slot = (tid < 32) ? rA[tid] : rB[tid - 32];
        bool own = true;
        if (tid >= 32) {
            int j = tid - 32;
            if (slot < nb0) own = false;          // covered by rA side
            else for (int i = 0; i < j; i++) if (rB[i] == slot) { own = false; break; }
        }
        if (own) {
            int s = slot;
            for (int t = 31; t >= 0; t--) {
                if (s == rA[t]) s = rB[t];
                else if (s == rB[t]) s = rA[t];
            }
            if (s != slot) {
                int k = atomicAdd(&s_cnt, 1);
                dsts[k] = slot; srcs[k] = s;
            }
        }
    }
    // cooperative load of L11 (unit-lower factor of panel kb diag block)
    float* L11 = sm;                                      // 32*33
    for (int l = tid; l < 32 * 32; l += 256)
        L11[(l >> 5) * 33 + (l & 31)] = A[(size_t)(col0 + (l >> 5)) * N + col0 + (l & 31)];
    __syncthreads();
    int cnt = s_cnt;

    if (blockIdx.x == 0) {
        // ================= combo block: cols [nb0, nb0+32) =================
        float* a12 = sm + 1056;                  // 32 x 36
        float* LsT = sm + 1056 + 1152;           // 32 x 132
        float* sp  = sm + 1056 + 1152 + 4224;    // Ru x 33
        int Ru = N - nb0;
        int RR = N - col0;
        // permuted gather (identity pass + fixups; sources live only in global)
        for (int l = tid; l < RR * 32; l += 256) {
            int r = l >> 5, c = l & 31;
            float v = A[(size_t)(col0 + r) * N + nb0 + c];
            if (r < 32) a12[r * 36 + c] = v;
            else        sp[(r - 32) * 33 + c] = v;
        }
        __syncthreads();
        for (int l = tid; l < cnt * 32; l += 256) {
            int k = l >> 5, c = l & 31;
            int dst = dsts[k] - col0;
            float v = A[(size_t)srcs[k] * N + nb0 + c];
            if (dst < 32) a12[dst * 36 + c] = v;
            else          sp[(dst - 32) * 33 + c] = v;
        }
        __syncthreads();
        // trsm: U12 = L11^{-1} A12 (32 cols)
        if (tid < 32) {
            int c = tid;
            float u[32];
            #pragma unroll
            for (int j = 0; j < 32; j++) {
                float s = a12[j * 36 + c];
                #pragma unroll
                for (int i = 0; i < 31; i++)
                    if (i < j) s -= L11[j * 33 + i] * u[i];
                u[j] = s;
                a12[j * 36 + c] = s;
            }
        }
        __syncthreads();
        // update sp -= L21 @ U12 (tiles of 128 rows, 4x4 per thread)
        int ntile = (Ru + 127) >> 7;
        int tx = tid & 7, ty = tid >> 3;
        for (int t0 = 0; t0 < ntile; t0++) {
            int r0 = t0 * 128;
            for (int l = tid; l < 128 * 32; l += 256) {
                int r = l >> 5, kk = l & 31;
                int gr = nb0 + r0 + r;
                LsT[kk * 132 + r] = (gr < N) ? A[(size_t)gr * N + col0 + kk] : 0.0f;
            }
            __syncthreads();
            float acc[4][4] = {};
            #pragma unroll
            for (int kk = 0; kk < 32; kk++) {
                float4 a = *(const float4*)&LsT[kk * 132 + ty * 4];
                float4 b = *(const float4*)&a12[kk * 36 + tx * 4];
                float av[4] = {a.x, a.y, a.z, a.w};
                float bv[4] = {b.x, b.y, b.z, b.w};
                #pragma unroll
                for (int i = 0; i < 4; i++)
                    #pragma unroll
                    for (int jj = 0; jj < 4; jj++)
                        acc[i][jj] = fmaf(av[i], bv[jj], acc[i][jj]);
            }
            #pragma unroll
            for (int i = 0; i < 4; i++) {
                int r = r0 + ty * 4 + i;
                if (r < Ru) {
                    #pragma unroll
                    for (int jj = 0; jj < 4; jj++)
                        sp[r * 33 + tx * 4 + jj] -= acc[i][jj];
                }
            }
            __syncthreads();
        }
        // factor panel kb+1 in smem, emit pivots (parity^1) + score
        factor_inplace(sp, Ru, m, nb0, par ^ 1, false);
        __syncthreads();
        for (int l = tid; l < Ru * 32; l += 256) {
            int r = l >> 5, c = l & 31;
            A[(size_t)(nb0 + r) * N + nb0 + c] = sp[r * 33 + c];
        }
    } else {
        // ================= rest strip: 128 cols =================
        float* Bs    = sm + 1056;                 // 32 x 128
        float* LsT   = sm + 1056 + 4096;          // 32 x 132
        float* stage = sm + 1056;                 // 64 x 128 (aliases Bs+LsT)
        int c0 = nb0 + NB + (blockIdx.x - 1) * 128;
        // apply row permutation to this strip's columns (stage then write)
        for (int l = tid; l < cnt * 128; l += 256) {
            int k = l >> 7, c = l & 127;
            int cc = c0 + c;
            stage[k * 128 + c] = (cc < N) ? A[(size_t)srcs[k] * N + cc] : 0.0f;
        }
        __syncthreads();
        for (int l = tid; l < cnt * 128; l += 256) {
            int k = l >> 7, c = l & 127;
            int cc = c0 + c;
            if (cc < N) A[(size_t)dsts[k] * N + cc] = stage[k * 128 + c];
        }
        __syncthreads();
        // trsm into Bs (stage dead now)
        if (tid < 128) {
            int cc = c0 + tid;
            if (cc < N) {
                float u[32];
                #pragma unroll
                for (int j = 0; j < 32; j++) {
                    float s = A[(size_t)(col0 + j) * N + cc];
                    #pragma unroll
                    for (int i = 0; i < 31; i++)
                        if (i < j) s -= L11[j * 33 + i] * u[i];
                    u[j] = s;
                    Bs[j * 128 + tid] = s;
                }
            } else {
                #pragma unroll
                for (int j = 0; j < 32; j++) Bs[j * 128 + tid] = 0.0f;
            }
        }
        __syncthreads();
        // update A22 tiles (128 rows x 128 cols, 8x8 per thread)
        int Ru = N - nb0;
        int ntile = (Ru + 127) >> 7;
        int tx = tid & 15, ty = tid >> 4;
        for (int t0 = 0; t0 < ntile; t0++) {
            int r0 = t0 * 128;
            for (int l = tid; l < 128 * 32; l += 256) {
                int r = l >> 5, kk = l & 31;
                int gr = nb0 + r0 + r;
                LsT[kk * 132 + r] = (gr < N) ? A[(size_t)gr * N + col0 + kk] : 0.0f;
            }
            __syncthreads();
            float acc[8][8] = {};
            #pragma unroll
            for (int kk = 0; kk < 32; kk++) {
                float a[8], b[8];
                *(float4*)&a[0] = *(const float4*)&LsT[kk * 132 + ty * 8];
                *(float4*)&a[4] = *(const float4*)&LsT[kk * 132 + ty * 8 + 4];
                *(float4*)&b[0] = *(const float4*)&Bs[kk * 128 + tx * 8];
                *(float4*)&b[4] = *(const float4*)&Bs[kk * 128 + tx * 8 + 4];
                #pragma unroll
                for (int i = 0; i < 8; i++)
                    #pragma unroll
                    for (int jj = 0; jj < 8; jj++)
                        acc[i][jj] = fmaf(a[i], b[jj], acc[i][jj]);
            }
            int gr0 = nb0 + r0 + ty * 8, gc0 = c0 + tx * 8;
            if (gc0 < N) {
                #pragma unroll
                for (int i = 0; i < 8; i++) {
                    int gr = gr0 + i;
                    if (gr < N) {
                        float4* p0 = (float4*)&A[(size_t)gr * N + gc0];
                        float4 v0 = p0[0], v1 = p0[1];
                        v0.x -= acc[i][0]; v0.y -= acc[i][1];
                        v0.z -= acc[i][2]; v0.w -= acc[i][3];
                        v1.x -= acc[i][4]; v1.y -= acc[i][5];
                        v1.z -= acc[i][6]; v1.w -= acc[i][7];
                        p0[0] = v0; p0[1] = v1;
                    }
                }
            }
            __syncthreads();
        }
    }
}

// ---------------- tail: apply panel 27 to last 128 cols + factor 128x128 ------
__global__ __launch_bounds__(256) void tail_kernel() {
    extern __shared__ float sm[];
    __shared__ int rA[32], rB[32];
    __shared__ int dsts[64], srcs[64];
    __shared__ int s_cnt;
    __shared__ float rv[8];
    __shared__ int   rr[8];
    __shared__ float s_u;
    __shared__ int   s_p;
    int tid = threadIdx.x, m = blockIdx.x;
    float* A = g_lu + (size_t)m * NN;
    const int col0 = 864, nb0 = 896;     // panel 27
    const int par = 1;                   // 27 & 1

    if (tid < 32) { rA[tid] = col0 + tid; rB[tid] = g_piv[par][m][tid]; }
    if (tid == 0) s_cnt = 0;
    __syncthreads();
    if (tid < 64) {
        int slot = (tid < 32) ? rA[tid] : rB[tid - 32];
        bool own = true;
        if (tid >= 32) {
            int j = tid - 32;
            if (slot < nb0) own = false;
            else for (int i = 0; i < j; i++) if (rB[i] == slot) { own = false; break; }
        }
        if (own) {
            int s = slot;
            for (int t = 31; t >= 0; t--) {
                if (s == rA[t]) s = rB[t];
                else if (s == rB[t]) s = rA[t];
            }
            if (s != slot) {
                int k = atomicAdd(&s_cnt, 1);
                dsts[k] = slot; srcs[k] = s;
            }
        }
    }
    float* L11 = sm;                 // 32*33
    float* LsT = sm + 1056;          // 32*132
    float* st  = sm + 1056 + 4224;   // 160*132
    for (int l = tid; l < 32 * 32; l += 256)
        L11[(l >> 5) * 33 + (l & 31)] = A[(size_t)(col0 + (l >> 5)) * N + col0 + (l & 31)];
    __syncthreads();
    int cnt = s_cnt;
    // gather rows [864,1024) x cols [896,1024) with permutation
    for (int l = tid; l < 160 * 128; l += 256) {
        int r = l >> 7, c = l & 127;
        st[r * 132 + c] = A[(size_t)(col0 + r) * N + nb0 + c];
    }
    __syncthreads();
    for (int l = tid; l < cnt * 128; l += 256) {
        int k = l >> 7, c = l & 127;
        st[(dsts[k] - col0) * 132 + c] = A[(size_t)srcs[k] * N + nb0 + c];
    }
    __syncthreads();
    // trsm on top 32 rows
    if (tid < 128) {
        int c = tid;
        float u[32];
        #pragma unroll
        for (int j = 0; j < 32; j++) {
            float s = st[j * 132 + c];
            #pragma unroll
            for (int i = 0; i < 31; i++)
                if (i < j) s -= L11[j * 33 + i] * u[i];
            u[j] = s;
            st[j * 132 + c] = s;
        }
    }
    // L21 tile
    for (int l = tid; l < 128 * 32; l += 256) {
        int r = l >> 5, kk = l & 31;
        LsT[kk * 132 + r] = A[(size_t)(nb0 + r) * N + col0 + kk];
    }
    __syncthreads();
    // update bottom 128 rows: st22 -= L21 @ U12
    {
        int tx = tid & 15, ty = tid >> 4;
        float acc[8][8] = {};
        #pragma unroll
        for (int kk = 0; kk < 32; kk++) {
            float a[8], b[8];
            *(float4*)&a[0] = *(const float4*)&LsT[kk * 132 + ty * 8];
            *(float4*)&a[4] = *(const float4*)&LsT[kk * 132 + ty * 8 + 4];
            *(float4*)&b[0] = *(const float4*)&st[kk * 132 + tx * 8];
            *(float4*)&b[4] = *(const float4*)&st[kk * 132 + tx * 8 + 4];
            #pragma unroll
            for (int i = 0; i < 8; i++)
                #pragma unroll
                for (int jj = 0; jj < 8; jj++)
                    acc[i][jj] = fmaf(a[i], b[jj], acc[i][jj]);
        }
        #pragma unroll
        for (int i = 0; i < 8; i++)
            #pragma unroll
            for (int jj = 0; jj < 8; jj++)
                st[(32 + ty * 8 + i) * 132 + tx * 8 + jj] -= acc[i][jj];
    }
    __syncthreads();
    // full pivoted factorization of trailing 128x128 (logdet only, no writeback)
    float logsum = 0.0f;
    for (int j = 0; j < 128; j++) {
        float bv = -1.0f; int br = j;
        if (tid < 128 && tid >= j) {
            bv = fabsf(st[(32 + tid) * 132 + j]);
            br = tid;
        }
        #pragma unroll
        for (int off = 16; off; off >>= 1) {
            float ov = __shfl_down_sync(0xffffffffu, bv, off);
            int   orr = __shfl_down_sync(0xffffffffu, br, off);
            if (ov > bv || (ov == bv && orr < br)) { bv = ov; br = orr; }
        }
        if ((tid & 31) == 0) { rv[tid >> 5] = bv; rr[tid >> 5] = br; }
        __syncthreads();
        if (tid == 0) {
            float b0 = rv[0]; int r0 = rr[0];
            for (int w = 1; w < 8; w++)
                if (rv[w] > b0 || (rv[w] == b0 && rr[w] < r0)) { b0 = rv[w]; r0 = rr[w]; }
            s_p = r0;
            s_u = st[(32 + r0) * 132 + j];
            logsum += logf(fabsf(s_u));
        }
        __syncthreads();
        int p = s_p;
        float u = s_u;
        if (tid < 128 && p != j) {
            float t = st[(32 + j) * 132 + tid];
            st[(32 + j) * 132 + tid] = st[(32 + p) * 132 + tid];
            st[(32 + p) * 132 + tid] = t;
        }
        __syncthreads();
        if (tid < 128 && tid > j) {
            float lij = st[(32 + tid) * 132 + j] / u;
            for (int c = j + 1; c < 128; c++)
                st[(32 + tid) * 132 + c] -= lij * st[(32 + j) * 132 + c];
        }
        __syncthreads();
    }
    if (tid == 0) g_scores[m] += logsum;
}

// ---------------- top-8 selection + effective-weight collapse -----------------
__global__ void topk_kernel(const int* __restrict__ flags_i32,
                            const float* __restrict__ W1, const float* __restrict__ b1,
                            const float* __restrict__ W2, const float* __restrict__ b2) {
    if (threadIdx.x != 0) return;
    const unsigned char* flags_u8 = (const unsigned char*)flags_i32;
    int w0 = flags_i32[0];
    bool as_bytes = (w0 > 1) || (w0 < 0);
    int f[16];
    for (int i = 0; i < 16; i++)
        f[i] = as_bytes ? (flags_u8[i] != 0) : (flags_i32[i] != 0);
    int s = 0;
    for (int i = 0; i < 16; i++) s += f[i];
    g_gate = (s >= 4) ? 1 : 0;
    const float NEG_INF = -__int_as_float(0x7f800000);
    float sc[16];
    for (int i = 0; i < 16; i++) sc[i] = f[i] ? g_scores[i] : NEG_INF;
    bool used[16] = {};
    for (int k = 0; k < 8; k++) {
        float best = NEG_INF;
        int bi = -1;
        for (int i = 0; i < 16; i++)
            if (!used[i] && (bi < 0 || sc[i] > best)) { best = sc[i]; bi = i; }
        used[bi] = true;
        g_top[k] = bi;
    }
    for (int c = 0; c < 10; c++) {
        float a = 0.0f;
        for (int h = 0; h < 16; h++) a += W2[h] * W1[h * 10 + c];
        g_weff[c] = a;
    }
    float be = b2[0];
    for (int h = 0; h < 16; h++) be += W2[h] * b1[h];
    g_weff[10] = be;
}

// ---------------- Y combos ----------------------------------------------------
__global__ void ycombo_kernel(const float* __restrict__ x) {
    const float* X1 = x + (size_t)g_top[1] * NN;
    const float* X2 = x + (size_t)g_top[2] * NN;
    const float* X3 = x + (size_t)g_top[3] * NN;
    float w0 = g_weff[0], w1 = g_weff[1], w2 = g_weff[2];
    float w3 = g_weff[3], w4 = g_weff[4], w5 = g_weff[5];
    for (int e = blockIdx.x * blockDim.x + threadIdx.x; e < NN;
         e += gridDim.x * blockDim.x) {
        float a = X1[e], b = X2[e], c = X3[e];
        g_y[e]          = w0 * a + w1 * b + w2 * c;
        g_y[NN + e]     = w3 * b + w4 * c;
        g_y[2 * NN + e] = w5 * c;
    }
}

// ---------------- pair GEMM: X[0..2] (1024x3072) @ Y (3072x1024), split-K=2 ---
__global__ __launch_bounds__(256) void pair_gemm(const float* __restrict__ x) {
    __shared__ float As[16][132];
    __shared__ float Bs[16][128];
    int z = blockIdx.z;
    int row0 = blockIdx.y * 128, c0 = blockIdx.x * 128;
    const float* A0 = x + (size_t)g_top[0] * NN;
    const float* A1 = x + (size_t)g_top[1] * NN;
    const float* A2 = x + (size_t)g_top[2] * NN;
    int tid = threadIdx.x;
    float acc[8][8] = {};
    int k0 = z * 1536;
    for (int kt = 0; kt < 96; kt++) {
        int kg = k0 + kt * 16;
        const float* Ap = (kg < 1024) ? A0 : ((kg < 2048) ? A1 : A2);
        int kl = kg & 1023;
        #pragma unroll
        for (int i = 0; i < 8; i++) {
            int l = tid + i * 256;
            int kk = l & 15, mm = l >> 4;
            As[kk][mm] = Ap[(size_t)(row0 + mm) * N + kl + kk];
        }
        #pragma unroll
        for (int i = 0; i < 8; i++) {
            int l = tid + i * 256;
            int nn = l & 127, kk = l >> 7;
            Bs[kk][nn] = g_y[(size_t)(kg + kk) * N + c0 + nn];
        }
        __syncthreads();
        int mm0 = (tid >> 4) * 8, nn0 = (tid & 15) * 8;
        #pragma unroll
        for (int kk = 0; kk < 16; kk++) {
            float a[8], b[8];
            *(float4*)&a[0] = *(const float4*)&As[kk][mm0];
            *(float4*)&a[4] = *(const float4*)&As[kk][mm0 + 4];
            *(float4*)&b[0] = *(const float4*)&Bs[kk][nn0];
            *(float4*)&b[4] = *(const float4*)&Bs[kk][nn0 + 4];
            #pragma unroll
            for (int i = 0; i < 8; i++)
                #pragma unroll
                for (int j = 0; j < 8; j++)
                    acc[i][j] = fmaf(a[i], b[j], acc[i][j]);
        }
        __syncthreads();
    }
    float* P = g_part + (size_t)z * NN;
    int mm0 = (tid >> 4) * 8, nn0 = (tid & 15) * 8;
    #pragma unroll
    for (int i = 0; i < 8; i++) {
        float4 v0 = {acc[i][0], acc[i][1], acc[i][2], acc[i][3]};
        float4 v1 = {acc[i][4], acc[i][5], acc[i][6], acc[i][7]};
        size_t off = (size_t)(row0 + mm0 + i) * N + c0 + nn0;
        *(float4*)&P[off] = v0;
        *(float4*)&P[off + 4] = v1;
    }
}

// ---------------- epilogue ----------------------------------------------------
__global__ void final_kernel(const float* __restrict__ x, float* __restrict__ out,
                             int out_size) {
    int gate = g_gate;
    const float* P4 = x + (size_t)g_top[4] * NN;
    const float* P5 = x + (size_t)g_top[5] * NN;
    const float* P6 = x + (size_t)g_top[6] * NN;
    const float* P7 = x + (size_t)g_top[7] * NN;
    float w6 = g_weff[6], w7 = g_weff[7], w8 = g_weff[8], w9 = g_weff[9];
    float be = g_weff[10];
    for (int i = blockIdx.x * blockDim.x + threadIdx.x; i < out_size;
         i += gridDim.x * blockDim.x) {
        if (i < NN) {
            float s = g_part[i] + g_part[NN + i]
                    + w6 * P4[i] + w7 * P5[i] + w8 * P6[i] + w9 * P7[i] + be;
            out[i] = gate ? (s / (1.0f + expf(-s))) : 0.0f;
        } else {
            out[i] = gate ? 1.0f : 0.0f;
        }
    }
}

// ---------------- host driver -------------------------------------------------
extern "C" void kernel_launch(void* const* d_in, const int* in_sizes, int n_in,
                              void* d_out, int out_size) {
    const float* x = (const float*)d_in[0];
    const int* flags = (const int*)d_in[1];
    const float* W1 = (const float*)d_in[2];
    const float* b1 = (const float*)d_in[3];
    const float* W2 = (const float*)d_in[4];
    const float* b2 = (const float*)d_in[5];
    float* out = (float*)d_out;

    cudaFuncSetAttribute(panel0_kernel, cudaFuncAttributeMaxDynamicSharedMemorySize,
                         N * 33 * 4);
    cudaFuncSetAttribute(step_kernel, cudaFuncAttributeMaxDynamicSharedMemorySize,
                         156 * 1024);
    cudaFuncSetAttribute(tail_kernel, cudaFuncAttributeMaxDynamicSharedMemorySize,
                         (1056 + 4224 + 160 * 132) * 4);

    init_kernel<<<2048, 256>>>((const float4*)x);
    panel0_kernel<<<16, 256, N * 33 * 4>>>();

    for (int kb = 0; kb < NSTEP; kb++) {
        int nb0 = kb * NB + NB;
        int restcols = N - nb0 - NB;
        int nrest = (restcols + 127) / 128;
        size_t comboF = 1056 + 1152 + 4224 + (size_t)(N - nb0) * 33;
        size_t restF  = 1056 + 8320;
        size_t dyn = (comboF > restF ? comboF : restF) * 4;
        step_kernel<<<dim3(1 + nrest, 16), 256, dyn>>>(kb);
    }

    tail_kernel<<<16, 256, (1056 + 4224 + 160 * 132) * 4>>>();
    topk_kernel<<<1, 32>>>(flags, W1, b1, W2, b2);
    ycombo_kernel<<<1024, 256>>>(x);
    pair_gemm<<<dim3(8, 8, 2), 256>>>(x);
    final_kernel<<<1024, 256>>>(x, out, out_size);
}